// round 16
// baseline (speedup 1.0000x reference)
#include <cuda_runtime.h>
#include <cuda_fp16.h>
#include <math.h>

#define BB 2
#define NN 2048
#define MM 2048
#define DD 1024
#define HH 16
#define HD 64
#define FF 4096
#define EPS 1e-5f

typedef __half h16;

// ---------------- scratch (allocation-free device globals) ----------------
__device__ float gX[(size_t)BB * NN * DD];   // attn out + residual

__device__ h16 gqh[(size_t)BB * NN * DD];    // query fp16
__device__ h16 gch[(size_t)BB * MM * DD];    // context fp16
__device__ h16 gWq[DD * DD], gWk[DD * DD], gWv[DD * DD];
__device__ h16 gF1[(size_t)DD * FF], gF2[(size_t)FF * DD];
__device__ h16 gQh[(size_t)BB * NN * DD];    // LN(Q) * (log2e/8)
__device__ h16 gKh[(size_t)BB * MM * DD];    // LN(K)
__device__ h16 gVh[(size_t)BB * MM * DD];    // V
__device__ h16 gLh[(size_t)BB * NN * DD];    // pre-MLP LN
__device__ h16 gHh[(size_t)BB * NN * FF];    // mlp hidden

__device__ __forceinline__ float gelu_exact(float x) {
    return 0.5f * x * (1.0f + erff(x * 0.70710678118654752f));
}

// ---------------- fp16 helpers ----------------
__device__ __forceinline__ unsigned pack2h(float x0, float x1) {
    unsigned r;
    asm("cvt.rn.f16x2.f32 %0, %1, %2;" : "=r"(r) : "f"(x1), "f"(x0));
    return r;
}
__device__ __forceinline__ unsigned h2exp2u(unsigned x) {
    unsigned r;
    asm("ex2.approx.f16x2 %0, %1;" : "=r"(r) : "r"(x));
    return r;
}

// ---------------- mma / ldmatrix / cp.async ----------------
__device__ __forceinline__ void mma16(float* c, const unsigned* a, unsigned b0, unsigned b1) {
    asm volatile(
        "mma.sync.aligned.m16n8k16.row.col.f32.f16.f16.f32 "
        "{%0,%1,%2,%3}, {%4,%5,%6,%7}, {%8,%9}, {%0,%1,%2,%3};"
        : "+f"(c[0]), "+f"(c[1]), "+f"(c[2]), "+f"(c[3])
        : "r"(a[0]), "r"(a[1]), "r"(a[2]), "r"(a[3]), "r"(b0), "r"(b1));
}
__device__ __forceinline__ void ldsm4(unsigned* r, const h16* p) {
    unsigned a = (unsigned)__cvta_generic_to_shared(p);
    asm volatile("ldmatrix.sync.aligned.m8n8.x4.shared.b16 {%0,%1,%2,%3}, [%4];"
                 : "=r"(r[0]), "=r"(r[1]), "=r"(r[2]), "=r"(r[3]) : "r"(a));
}
__device__ __forceinline__ void ldsm4t(unsigned* r, const h16* p) {
    unsigned a = (unsigned)__cvta_generic_to_shared(p);
    asm volatile("ldmatrix.sync.aligned.m8n8.x4.trans.shared.b16 {%0,%1,%2,%3}, [%4];"
                 : "=r"(r[0]), "=r"(r[1]), "=r"(r[2]), "=r"(r[3]) : "r"(a));
}
// L2->smem direct fill (.cg): keeps cp.async off the L1 fill path.
__device__ __forceinline__ void cpasync16(const h16* s, const h16* g) {
    unsigned sa = (unsigned)__cvta_generic_to_shared(s);
    asm volatile("cp.async.cg.shared.global [%0], [%1], 16;" ::"r"(sa), "l"(g));
}
#define CP_COMMIT() asm volatile("cp.async.commit_group;")
#define CP_WAIT2()  asm volatile("cp.async.wait_group 2;")
#define CP_WAIT1()  asm volatile("cp.async.wait_group 1;")

// ---------------- batched fp32 -> fp16 conversion ----------------
#define NCONV 7
struct ConvJobs {
    const float4* src[NCONV];
    unsigned* dst[NCONV];
    int n4[NCONV];
};
__global__ __launch_bounds__(256) void conv_batch(ConvJobs jb)
{
    const int j = blockIdx.y;
    const int n4 = jb.n4[j];
    const float4* __restrict__ x = jb.src[j];
    unsigned* __restrict__ h = jb.dst[j];
    for (int i = blockIdx.x * blockDim.x + threadIdx.x; i < n4;
         i += gridDim.x * blockDim.x) {
        float4 v = x[i];
        h[2 * i]     = pack2h(v.x, v.y);
        h[2 * i + 1] = pack2h(v.z, v.w);
    }
}

// ---------------------------------------------------------------------------
// GEMM tiling. Block tile 128x128xBK32, 256 threads, 8 warps (4 row x 2 col),
// warp tile 32x64, mma m16n8k16. FOUR-stage cp.async ring, consume 1 stage
// per barrier, prefetch distance 3 (absorbs L2/DRAM latency spikes).
// WAR safety: stage target buf+3 == buf-1 (mod 4), consumed in the previous
// iteration, staged strictly after this iteration's barrier.
// smem h16: A[4][128][40] | B[4][32][136] -> 75776 bytes (2 blocks/SM)
// ---------------------------------------------------------------------------
#define A_STR 40
#define B_STR 136
#define A_ST_SZ (128 * A_STR)
#define B_ST_SZ (32 * B_STR)
#define OFF_B (4 * A_ST_SZ)
#define GEMM_SMEM_BYTES ((OFF_B + 4 * B_ST_SZ) * 2)

#define GEMM_STAGE(s, k0)                                                     \
    do {                                                                      \
        const h16* ap_ = A + (size_t)(brow + ar) * K + (k0) + ac;             \
        h16* dh_ = &sm[(s) * A_ST_SZ + ar * A_STR + ac];                      \
        cpasync16(dh_, ap_);                                                  \
        cpasync16(dh_ + 8, ap_ + 8);                                          \
        size_t go_ = (size_t)((k0) + br_) * Nc + bcol + bc;                   \
        h16* db_ = &sm[OFF_B + (s) * B_ST_SZ + br_ * B_STR + bc];             \
        cpasync16(db_, B + go_);                                              \
        cpasync16(db_ + 64, B + go_ + 64);                                    \
    } while (0)

#define GEMM_COMPUTE(buf)                                                     \
    do {                                                                      \
        _Pragma("unroll")                                                     \
        for (int kk = 0; kk < 2; kk++) {                                      \
            unsigned ah[2][4];                                                \
            _Pragma("unroll")                                                 \
            for (int mt = 0; mt < 2; mt++) {                                  \
                int off = (buf) * A_ST_SZ + (wm + mt * 16 + lrow) * A_STR +   \
                          kk * 16 + lc8;                                      \
                ldsm4(ah[mt], &sm[off]);                                      \
            }                                                                 \
            _Pragma("unroll")                                                 \
            for (int pr = 0; pr < 4; pr++) {                                  \
                unsigned bh[4];                                               \
                int off = OFF_B + (buf) * B_ST_SZ + (kk * 16 + lrow) * B_STR + \
                          wn + pr * 16 + lc8;                                 \
                ldsm4t(bh, &sm[off]);                                         \
                _Pragma("unroll")                                             \
                for (int mt = 0; mt < 2; mt++) {                              \
                    mma16(acc[mt][2 * pr],     ah[mt], bh[0], bh[1]);         \
                    mma16(acc[mt][2 * pr + 1], ah[mt], bh[2], bh[3]);         \
                }                                                             \
            }                                                                 \
        }                                                                     \
    } while (0)

// 4-stage mainloop, T = K/32
#define GEMM_MAINLOOP()                                                       \
    do {                                                                      \
        const int T = K / 32;                                                 \
        GEMM_STAGE(0, 0);  CP_COMMIT();                                       \
        GEMM_STAGE(1, 32); CP_COMMIT();                                       \
        GEMM_STAGE(2, 64); CP_COMMIT();                                       \
        int buf = 0;                                                          \
        for (int it = 0; it < T; it++) {                                      \
            CP_WAIT2();                                                       \
            __syncthreads();                                                  \
            GEMM_COMPUTE(buf);                                                \
            if (it + 3 < T) {                                                 \
                int s3 = buf + 3; if (s3 >= 4) s3 -= 4;                       \
                GEMM_STAGE(s3, (it + 3) * 32);                                \
            }                                                                 \
            CP_COMMIT();                                                      \
            if (++buf == 4) buf = 0;                                          \
        }                                                                     \
    } while (0)

// ---------------------------------------------------------------------------
// Merged QKV projection: grid (24, 32). blockIdx.x>>3 selects Q|K|V.
// Q scaled by 0.125*log2(e): mma in attention then emits s*log2e directly.
// ---------------------------------------------------------------------------
#define QSCALE 0.18033688011112042f   // log2(e)/8

__global__ __launch_bounds__(256, 2) void qkv_tc(
    const h16* __restrict__ qh_, const h16* __restrict__ ch_,
    const h16* __restrict__ Wq, const h16* __restrict__ Wk,
    const h16* __restrict__ Wv,
    const float* __restrict__ Wqb, const float* __restrict__ Wkb,
    const float* __restrict__ Wvb,
    const float* __restrict__ qnw, const float* __restrict__ qnb,
    const float* __restrict__ knw, const float* __restrict__ knb,
    h16* __restrict__ Qo, h16* __restrict__ Ko, h16* __restrict__ Vo)
{
    extern __shared__ __align__(16) h16 sm[];
    const int tid = threadIdx.x, wid = tid >> 5, lane = tid & 31;
    const int g = lane >> 2, t = lane & 3;
    const int wm = (wid >> 1) * 32, wn = (wid & 1) * 64;
    const int which = blockIdx.x >> 3;
    const int bcol = (blockIdx.x & 7) * 128;
    const int brow = blockIdx.y * 128;
    const int lrow = lane & 15, lc8 = ((lane >> 4) & 1) * 8;
    const int Nc = DD, K = DD;

    const h16* A = (which == 0) ? qh_ : ch_;
    const h16* B = (which == 0) ? Wq : (which == 1) ? Wk : Wv;
    const float* bias = (which == 0) ? Wqb : (which == 1) ? Wkb : Wvb;
    h16* Ch = (which == 0) ? Qo : (which == 1) ? Ko : Vo;

    const int ar = tid >> 1, ac = (tid & 1) * 16;
    const int br_ = tid >> 3, bc = (tid & 7) * 8;

    float acc[2][8][4];
    #pragma unroll
    for (int i = 0; i < 2; i++)
        #pragma unroll
        for (int j = 0; j < 8; j++)
            #pragma unroll
            for (int q = 0; q < 4; q++) acc[i][j][q] = 0.0f;

    GEMM_MAINLOOP();

    if (which < 2) {
        const float* lnw = (which == 0) ? qnw : knw;
        const float* lnb = (which == 0) ? qnb : knb;
        const float lnsc = (which == 0) ? QSCALE : 1.0f;
        #pragma unroll
        for (int mt = 0; mt < 2; mt++) {
            float sA = 0.0f, qA = 0.0f, sB = 0.0f, qB = 0.0f;
            #pragma unroll
            for (int nt = 0; nt < 8; nt++) {
                const int hc = nt * 8 + 2 * t;
                float2 bv = *(const float2*)(bias + bcol + wn + hc);
                float a0 = acc[mt][nt][0] + bv.x;
                float a1 = acc[mt][nt][1] + bv.y;
                float a2 = acc[mt][nt][2] + bv.x;
                float a3 = acc[mt][nt][3] + bv.y;
                acc[mt][nt][0] = a0; acc[mt][nt][1] = a1;
                acc[mt][nt][2] = a2; acc[mt][nt][3] = a3;
                sA += a0 + a1; qA += a0 * a0 + a1 * a1;
                sB += a2 + a3; qB += a2 * a2 + a3 * a3;
            }
            sA += __shfl_xor_sync(0xffffffffu, sA, 1);
            sA += __shfl_xor_sync(0xffffffffu, sA, 2);
            qA += __shfl_xor_sync(0xffffffffu, qA, 1);
            qA += __shfl_xor_sync(0xffffffffu, qA, 2);
            sB += __shfl_xor_sync(0xffffffffu, sB, 1);
            sB += __shfl_xor_sync(0xffffffffu, sB, 2);
            qB += __shfl_xor_sync(0xffffffffu, qB, 1);
            qB += __shfl_xor_sync(0xffffffffu, qB, 2);
            const float muA = sA * (1.0f / 64.0f);
            const float muB = sB * (1.0f / 64.0f);
            const float rA = rsqrtf(qA * (1.0f / 64.0f) - muA * muA + EPS);
            const float rB = rsqrtf(qB * (1.0f / 64.0f) - muB * muB + EPS);
            const int r0 = brow + wm + mt * 16 + g;
            #pragma unroll
            for (int nt = 0; nt < 8; nt++) {
                const int hc = nt * 8 + 2 * t;
                const int c = bcol + wn + hc;
                float2 lw = *(const float2*)(lnw + hc);
                float2 lb = *(const float2*)(lnb + hc);
                float y0 = ((acc[mt][nt][0] - muA) * rA * lw.x + lb.x) * lnsc;
                float y1 = ((acc[mt][nt][1] - muA) * rA * lw.y + lb.y) * lnsc;
                float y2 = ((acc[mt][nt][2] - muB) * rB * lw.x + lb.x) * lnsc;
                float y3 = ((acc[mt][nt][3] - muB) * rB * lw.y + lb.y) * lnsc;
                *(unsigned*)(Ch + (size_t)r0 * Nc + c)       = pack2h(y0, y1);
                *(unsigned*)(Ch + (size_t)(r0 + 8) * Nc + c) = pack2h(y2, y3);
            }
        }
    } else {
        #pragma unroll
        for (int nt = 0; nt < 8; nt++) {
            const int c = bcol + wn + nt * 8 + 2 * t;
            float2 bv = *(const float2*)(bias + c);
            #pragma unroll
            for (int mt = 0; mt < 2; mt++) {
                const int r0 = brow + wm + mt * 16 + g;
                *(unsigned*)(Ch + (size_t)r0 * Nc + c) =
                    pack2h(acc[mt][nt][0] + bv.x, acc[mt][nt][1] + bv.y);
                *(unsigned*)(Ch + (size_t)(r0 + 8) * Nc + c) =
                    pack2h(acc[mt][nt][2] + bv.x, acc[mt][nt][3] + bv.y);
            }
        }
    }
}

// ---------------------------------------------------------------------------
// fp16 GEMM for MLP, templated epilogue.
// ---------------------------------------------------------------------------
template <int EPI>
__global__ __launch_bounds__(256, 2) void gemm_tc(
    const h16* __restrict__ A, const h16* __restrict__ B,
    const float* __restrict__ bias, const float* __restrict__ Res,
    float* __restrict__ Cf, h16* __restrict__ Ch, int Nc, int K)
{
    extern __shared__ __align__(16) h16 sm[];
    const int tid = threadIdx.x, wid = tid >> 5, lane = tid & 31;
    const int g = lane >> 2, t = lane & 3;
    const int wm = (wid >> 1) * 32, wn = (wid & 1) * 64;
    const int brow = blockIdx.y * 128, bcol = blockIdx.x * 128;
    const int lrow = lane & 15, lc8 = ((lane >> 4) & 1) * 8;

    const int ar = tid >> 1, ac = (tid & 1) * 16;
    const int br_ = tid >> 3, bc = (tid & 7) * 8;

    float acc[2][8][4];
    #pragma unroll
    for (int i = 0; i < 2; i++)
        #pragma unroll
        for (int j = 0; j < 8; j++)
            #pragma unroll
            for (int q = 0; q < 4; q++) acc[i][j][q] = 0.0f;

    GEMM_MAINLOOP();

    #pragma unroll
    for (int nt = 0; nt < 8; nt++) {
        const int c = bcol + wn + nt * 8 + 2 * t;
        float2 bv = *(const float2*)(bias + c);
        #pragma unroll
        for (int mt = 0; mt < 2; mt++) {
            const int r0 = brow + wm + mt * 16 + g;
            float2 v0 = make_float2(acc[mt][nt][0] + bv.x, acc[mt][nt][1] + bv.y);
            float2 v1 = make_float2(acc[mt][nt][2] + bv.x, acc[mt][nt][3] + bv.y);
            if (EPI == 2) {
                float2 a0 = *(const float2*)(Res + (size_t)r0 * Nc + c);
                float2 a1 = *(const float2*)(Res + (size_t)(r0 + 8) * Nc + c);
                v0.x += a0.x; v0.y += a0.y; v1.x += a1.x; v1.y += a1.y;
                *(float2*)(Cf + (size_t)r0 * Nc + c) = v0;
                *(float2*)(Cf + (size_t)(r0 + 8) * Nc + c) = v1;
            } else {
                v0.x = gelu_exact(v0.x); v0.y = gelu_exact(v0.y);
                v1.x = gelu_exact(v1.x); v1.y = gelu_exact(v1.y);
                *(unsigned*)(Ch + (size_t)r0 * Nc + c) = pack2h(v0.x, v0.y);
                *(unsigned*)(Ch + (size_t)(r0 + 8) * Nc + c) = pack2h(v1.x, v1.y);
            }
        }
    }
}

// ---------------------------------------------------------------------------
// fp16 flash attention, bounded-max softmax with exp folded into Q scale:
// Q pre-scaled by log2e/8 so the mma emits s*log2e; P~ = exp2(s*log2e) is
// the UNNORMALIZED softmax numerator (constant factor cancels in the row
// sum). |s*log2e| <= 11.54 -> P~ <= 2980, safe in fp16.
// Q TILE = 128 rows, 256 threads / 8 warps, 2 blocks/SM (regs<=128).
// smem h16: K[3][64][72] | V[3][64][72] -> 55296 bytes
// ---------------------------------------------------------------------------
#define KV_STR 72
#define KV_ST_SZ (64 * KV_STR)
#define OFF_V (3 * KV_ST_SZ)
#define ATTN_SMEM_BYTES ((OFF_V + 3 * KV_ST_SZ) * 2)
#define ONES2 0x3C003C00u

__global__ __launch_bounds__(256, 2) void attn_tc(
    const h16* __restrict__ Qh_, const h16* __restrict__ Kh_,
    const h16* __restrict__ Vh_,
    const float* __restrict__ Res, float* __restrict__ Out)
{
    extern __shared__ __align__(16) h16 sm[];
    const int b = blockIdx.z, h = blockIdx.y, q0 = blockIdx.x * 128;
    const int tid = threadIdx.x, w = tid >> 5, lane = tid & 31;
    const int g = lane >> 2, t = lane & 3;
    const int lrow = lane & 15, lc8 = ((lane >> 4) & 1) * 8;
    const size_t hoff = (size_t)h * HD;

    const int sr = tid >> 2, sc = (tid & 3) * 2;
    auto stageKV = [&](int s, int c0) {
        size_t go = ((size_t)(b * MM + c0 + sr)) * DD + hoff;
        #pragma unroll
        for (int j = 0; j < 2; j++) {
            int c = (sc + j) * 8;
            int off = s * KV_ST_SZ + sr * KV_STR + c;
            cpasync16(&sm[off],         Kh_ + go + c);
            cpasync16(&sm[OFF_V + off], Vh_ + go + c);
        }
    };

    stageKV(0, 0); CP_COMMIT();
    stageKV(1, 64); CP_COMMIT();

    unsigned qh[4][4];
    {
        size_t r0 = ((size_t)(b * NN + q0 + w * 16 + g)) * DD + hoff;
        size_t r1 = r0 + 8 * DD;
        #pragma unroll
        for (int kk = 0; kk < 4; kk++) {
            int c0 = kk * 16 + 2 * t;
            qh[kk][0] = *(const unsigned*)(Qh_ + r0 + c0);
            qh[kk][1] = *(const unsigned*)(Qh_ + r1 + c0);
            qh[kk][2] = *(const unsigned*)(Qh_ + r0 + c0 + 8);
            qh[kk][3] = *(const unsigned*)(Qh_ + r1 + c0 + 8);
        }
    }

    float o[8][4];
    #pragma unroll
    for (int i = 0; i < 8; i++)
        #pragma unroll
        for (int j = 0; j < 4; j++) o[i][j] = 0.0f;
    float accl[4] = {0.0f, 0.0f, 0.0f, 0.0f};

    const int T = MM / 64;
    int buf = 0;
    for (int it = 0; it < T; it++) {
        CP_WAIT1();
        __syncthreads();

        float s[8][4];
        #pragma unroll
        for (int i = 0; i < 8; i++)
            #pragma unroll
            for (int j = 0; j < 4; j++) s[i][j] = 0.0f;

        #pragma unroll
        for (int kk = 0; kk < 4; kk++) {
            #pragma unroll
            for (int kp = 0; kp < 4; kp++) {
                unsigned kh[4];
                int off = buf * KV_ST_SZ + (kp * 16 + lrow) * KV_STR + kk * 16 + lc8;
                ldsm4(kh, &sm[off]);
                mma16(s[2 * kp],     qh[kk], kh[0], kh[2]);
                mma16(s[2 * kp + 1], qh[kk], kh[1], kh[3]);
            }
        }

        // P~ = exp2(s) directly (s already includes the log2e/8 scale)
        #pragma unroll
        for (int kk = 0; kk < 4; kk++) {
            unsigned ph[4];
            ph[0] = h2exp2u(pack2h(s[2 * kk][0],     s[2 * kk][1]));
            ph[1] = h2exp2u(pack2h(s[2 * kk][2],     s[2 * kk][3]));
            ph[2] = h2exp2u(pack2h(s[2 * kk + 1][0], s[2 * kk + 1][1]));
            ph[3] = h2exp2u(pack2h(s[2 * kk + 1][2], s[2 * kk + 1][3]));
            mma16(accl, ph, ONES2, ONES2);
            #pragma unroll
            for (int dp = 0; dp < 4; dp++) {
                unsigned vh[4];
                int off = buf * KV_ST_SZ + (kk * 16 + lrow) * KV_STR + dp * 16 + lc8;
                ldsm4t(vh, &sm[OFF_V + off]);
                mma16(o[2 * dp],     ph, vh[0], vh[1]);
                mma16(o[2 * dp + 1], ph, vh[2], vh[3]);
            }
        }

        if (it + 2 < T) {
            int s2 = buf + 2; if (s2 >= 3) s2 -= 3;
            stageKV(s2, (it + 2) * 64);
        }
        CP_COMMIT();
        if (++buf == 3) buf = 0;
    }

    const float i0 = 1.0f / accl[0], i1 = 1.0f / accl[2];
    size_t base0 = ((size_t)(b * NN + q0 + w * 16 + g)) * DD + hoff;
    size_t base1 = base0 + 8 * DD;
    #pragma unroll
    for (int nt = 0; nt < 8; nt++) {
        int c = nt * 8 + 2 * t;
        float2 r0v = *(const float2*)(Res + base0 + c);
        float2 r1v = *(const float2*)(Res + base1 + c);
        float2 v0 = make_float2(o[nt][0] * i0 + r0v.x, o[nt][1] * i0 + r0v.y);
        float2 v1 = make_float2(o[nt][2] * i1 + r1v.x, o[nt][3] * i1 + r1v.y);
        *(float2*)(Out + base0 + c) = v0;
        *(float2*)(Out + base1 + c) = v1;
    }
}

// ---------------------------------------------------------------------------
// Row LayerNorm over D=1024 -> fp16.
// ---------------------------------------------------------------------------
__global__ __launch_bounds__(256) void row_ln_pl(
    const float* __restrict__ x, const float* __restrict__ w,
    const float* __restrict__ b, h16* __restrict__ yh)
{
    const int row = blockIdx.x;
    const int tid = threadIdx.x;
    float4 v = ((const float4*)(x + (size_t)row * DD))[tid];
    float s  = v.x + v.y + v.z + v.w;
    float ss = v.x * v.x + v.y * v.y + v.z * v.z + v.w * v.w;
    #pragma unroll
    for (int o = 16; o; o >>= 1) {
        s  += __shfl_xor_sync(0xffffffffu, s, o);
        ss += __shfl_xor_sync(0xffffffffu, ss, o);
    }
    __shared__ float smm[8], sm2[8];
    if ((tid & 31) == 0) { smm[tid >> 5] = s; sm2[tid >> 5] = ss; }
    __syncthreads();
    if (tid < 32) {
        float a  = (tid < 8) ? smm[tid] : 0.0f;
        float a2 = (tid < 8) ? sm2[tid] : 0.0f;
        #pragma unroll
        for (int o = 4; o; o >>= 1) {
            a  += __shfl_xor_sync(0xffffffffu, a, o);
            a2 += __shfl_xor_sync(0xffffffffu, a2, o);
        }
        if (tid == 0) { smm[0] = a; sm2[0] = a2; }
    }
    __syncthreads();
    float mu  = smm[0] * (1.0f / (float)DD);
    float var = sm2[0] * (1.0f / (float)DD) - mu * mu;
    float r = rsqrtf(var + EPS);
    float4 ww = ((const float4*)w)[tid];
    float4 bb = ((const float4*)b)[tid];
    float y0 = (v.x - mu) * r * ww.x + bb.x;
    float y1 = (v.y - mu) * r * ww.y + bb.y;
    float y2 = (v.z - mu) * r * ww.z + bb.z;
    float y3 = (v.w - mu) * r * ww.w + bb.w;
    size_t off = (size_t)row * DD + tid * 4;
    *(unsigned*)(yh + off)     = pack2h(y0, y1);
    *(unsigned*)(yh + off + 2) = pack2h(y2, y3);
}

// ---------------------------------------------------------------------------
extern "C" void kernel_launch(void* const* d_in, const int* in_sizes, int n_in,
                              void* d_out, int out_size)
{
    const float* query   = (const float*)d_in[0];
    const float* context = (const float*)d_in[1];
    const float* Wq_w = (const float*)d_in[4];
    const float* Wq_b = (const float*)d_in[5];
    const float* Wk_w = (const float*)d_in[6];
    const float* Wk_b = (const float*)d_in[7];
    const float* Wv_w = (const float*)d_in[8];
    const float* Wv_b = (const float*)d_in[9];
    const float* qn_w = (const float*)d_in[10];
    const float* qn_b = (const float*)d_in[11];
    const float* kn_w = (const float*)d_in[12];
    const float* kn_b = (const float*)d_in[13];
    const float* ffn_w = (const float*)d_in[14];
    const float* ffn_b = (const float*)d_in[15];
    const float* fc1_w = (const float*)d_in[16];
    const float* fc1_b = (const float*)d_in[17];
    const float* fc2_w = (const float*)d_in[18];
    const float* fc2_b = (const float*)d_in[19];
    float* out = (float*)d_out;

    float* X;
    h16 *qh, *ch, *Wq, *Wk, *Wv, *F1, *F2, *Qh, *Kh, *Vh, *Lh, *Hh;
    cudaGetSymbolAddress((void**)&X, gX);
    cudaGetSymbolAddress((void**)&qh, gqh); cudaGetSymbolAddress((void**)&ch, gch);
    cudaGetSymbolAddress((void**)&Wq, gWq); cudaGetSymbolAddress((void**)&Wk, gWk);
    cudaGetSymbolAddress((void**)&Wv, gWv);
    cudaGetSymbolAddress((void**)&F1, gF1); cudaGetSymbolAddress((void**)&F2, gF2);
    cudaGetSymbolAddress((void**)&Qh, gQh); cudaGetSymbolAddress((void**)&Kh, gKh);
    cudaGetSymbolAddress((void**)&Vh, gVh);
    cudaGetSymbolAddress((void**)&Lh, gLh); cudaGetSymbolAddress((void**)&Hh, gHh);

    static bool attr_done = false;
    if (!attr_done) {
        cudaFuncSetAttribute(qkv_tc, cudaFuncAttributeMaxDynamicSharedMemorySize,
                             GEMM_SMEM_BYTES);
        cudaFuncSetAttribute(gemm_tc<1>, cudaFuncAttributeMaxDynamicSharedMemorySize,
                             GEMM_SMEM_BYTES);
        cudaFuncSetAttribute(gemm_tc<2>, cudaFuncAttributeMaxDynamicSharedMemorySize,
                             GEMM_SMEM_BYTES);
        cudaFuncSetAttribute(attn_tc, cudaFuncAttributeMaxDynamicSharedMemorySize,
                             ATTN_SMEM_BYTES);
        attr_done = true;
    }

    const int Rows = BB * NN;  // 4096
    const size_t actN = (size_t)BB * NN * DD;

    ConvJobs jb;
    jb.src[0] = (const float4*)query;   jb.dst[0] = (unsigned*)qh; jb.n4[0] = (int)(actN / 4);
    jb.src[1] = (const float4*)context; jb.dst[1] = (unsigned*)ch; jb.n4[1] = (int)(actN / 4);
    jb.src[2] = (const float4*)Wq_w;    jb.dst[2] = (unsigned*)Wq; jb.n4[2] = DD * DD / 4;
    jb.src[3] = (const float4*)Wk_w;    jb.dst[3] = (unsigned*)Wk; jb.n4[3] = DD * DD / 4;
    jb.src[4] = (const float4*)Wv_w;    jb.dst[4] = (unsigned*)Wv; jb.n4[4] = DD * DD / 4;
    jb.src[5] = (const float4*)fc1_w;   jb.dst[5] = (unsigned*)F1; jb.n4[5] = (int)((size_t)DD * FF / 4);
    jb.src[6] = (const float4*)fc2_w;   jb.dst[6] = (unsigned*)F2; jb.n4[6] = (int)((size_t)FF * DD / 4);
    conv_batch<<<dim3(1024, NCONV), 256>>>(jb);

    // merged QKV projections (Q/K with fused per-head LN; Q scaled by log2e/8)
    qkv_tc<<<dim3(24, Rows / 128), 256, GEMM_SMEM_BYTES>>>(
        qh, ch, Wq, Wk, Wv, Wq_b, Wk_b, Wv_b,
        qn_w, qn_b, kn_w, kn_b, Qh, Kh, Vh);

    // flash attention + residual -> X (fp32); q-tile 128, 256 threads
    attn_tc<<<dim3(NN / 128, HH, BB), 256, ATTN_SMEM_BYTES>>>(Qh, Kh, Vh, query, X);

    // pre-MLP LN -> fp16
    row_ln_pl<<<Rows, 256>>>(X, ffn_w, ffn_b, Lh);

    // fc1 + GELU -> fp16
    gemm_tc<1><<<dim3(FF / 128, Rows / 128), 256, GEMM_SMEM_BYTES>>>(
        Lh, F1, fc1_b, nullptr, nullptr, Hh, FF, DD);
    // fc2 + residual(X) -> out (fp32)
    gemm_tc<2><<<dim3(DD / 128, Rows / 128), 256, GEMM_SMEM_BYTES>>>(
        Hh, F2, fc2_b, X, out, nullptr, DD, FF);
}

// round 17
// speedup vs baseline: 1.0132x; 1.0132x over previous
#include <cuda_runtime.h>
#include <cuda_fp16.h>
#include <math.h>

#define BB 2
#define NN 2048
#define MM 2048
#define DD 1024
#define HH 16
#define HD 64
#define FF 4096
#define EPS 1e-5f

typedef __half h16;

// ---------------- scratch (allocation-free device globals) ----------------
__device__ float gX[(size_t)BB * NN * DD];   // attn out + residual

__device__ h16 gqh[(size_t)BB * NN * DD];    // query fp16
__device__ h16 gch[(size_t)BB * MM * DD];    // context fp16
__device__ h16 gWq[DD * DD], gWk[DD * DD], gWv[DD * DD];
__device__ h16 gF1[(size_t)DD * FF], gF2[(size_t)FF * DD];
__device__ h16 gQh[(size_t)BB * NN * DD];    // LN(Q) * (log2e/8)
__device__ h16 gKh[(size_t)BB * MM * DD];    // LN(K)
__device__ h16 gVh[(size_t)BB * MM * DD];    // V
__device__ h16 gLh[(size_t)BB * NN * DD];    // pre-MLP LN
__device__ h16 gHh[(size_t)BB * NN * FF];    // mlp hidden

__device__ __forceinline__ float gelu_exact(float x) {
    return 0.5f * x * (1.0f + erff(x * 0.70710678118654752f));
}

// ---------------- fp16 helpers ----------------
__device__ __forceinline__ unsigned pack2h(float x0, float x1) {
    unsigned r;
    asm("cvt.rn.f16x2.f32 %0, %1, %2;" : "=r"(r) : "f"(x1), "f"(x0));
    return r;
}
__device__ __forceinline__ unsigned h2exp2u(unsigned x) {
    unsigned r;
    asm("ex2.approx.f16x2 %0, %1;" : "=r"(r) : "r"(x));
    return r;
}

// ---------------- mma / ldmatrix / cp.async ----------------
__device__ __forceinline__ void mma16(float* c, const unsigned* a, unsigned b0, unsigned b1) {
    asm volatile(
        "mma.sync.aligned.m16n8k16.row.col.f32.f16.f16.f32 "
        "{%0,%1,%2,%3}, {%4,%5,%6,%7}, {%8,%9}, {%0,%1,%2,%3};"
        : "+f"(c[0]), "+f"(c[1]), "+f"(c[2]), "+f"(c[3])
        : "r"(a[0]), "r"(a[1]), "r"(a[2]), "r"(a[3]), "r"(b0), "r"(b1));
}
__device__ __forceinline__ void ldsm4(unsigned* r, const h16* p) {
    unsigned a = (unsigned)__cvta_generic_to_shared(p);
    asm volatile("ldmatrix.sync.aligned.m8n8.x4.shared.b16 {%0,%1,%2,%3}, [%4];"
                 : "=r"(r[0]), "=r"(r[1]), "=r"(r[2]), "=r"(r[3]) : "r"(a));
}
__device__ __forceinline__ void ldsm4t(unsigned* r, const h16* p) {
    unsigned a = (unsigned)__cvta_generic_to_shared(p);
    asm volatile("ldmatrix.sync.aligned.m8n8.x4.trans.shared.b16 {%0,%1,%2,%3}, [%4];"
                 : "=r"(r[0]), "=r"(r[1]), "=r"(r[2]), "=r"(r[3]) : "r"(a));
}
// L2->smem direct fill (.cg): keeps cp.async off the L1 fill path.
__device__ __forceinline__ void cpasync16(const h16* s, const h16* g) {
    unsigned sa = (unsigned)__cvta_generic_to_shared(s);
    asm volatile("cp.async.cg.shared.global [%0], [%1], 16;" ::"r"(sa), "l"(g));
}
#define CP_COMMIT() asm volatile("cp.async.commit_group;")
#define CP_WAIT1()  asm volatile("cp.async.wait_group 1;")

// ---------------- batched fp32 -> fp16 conversion ----------------
#define NCONV 7
struct ConvJobs {
    const float4* src[NCONV];
    unsigned* dst[NCONV];
    int n4[NCONV];
};
__global__ __launch_bounds__(256) void conv_batch(ConvJobs jb)
{
    const int j = blockIdx.y;
    const int n4 = jb.n4[j];
    const float4* __restrict__ x = jb.src[j];
    unsigned* __restrict__ h = jb.dst[j];
    for (int i = blockIdx.x * blockDim.x + threadIdx.x; i < n4;
         i += gridDim.x * blockDim.x) {
        float4 v = x[i];
        h[2 * i]     = pack2h(v.x, v.y);
        h[2 * i + 1] = pack2h(v.z, v.w);
    }
}

// ---------------------------------------------------------------------------
// GEMM tiling (R13/R15 champion config). Block tile 128x128xBK32, 256 threads,
// 8 warps (4 row x 2 col), warp tile 32x64, mma m16n8k16. 3-stage cp.async
// pipeline, ONE __syncthreads per k-step.
// smem h16: A[3][128][40] | B[3][32][136] -> 56832 bytes (2 blocks/SM)
// ---------------------------------------------------------------------------
#define A_STR 40
#define B_STR 136
#define A_ST_SZ (128 * A_STR)
#define B_ST_SZ (32 * B_STR)
#define OFF_B (3 * A_ST_SZ)
#define GEMM_SMEM_BYTES ((OFF_B + 3 * B_ST_SZ) * 2)

#define GEMM_STAGE(s, k0)                                                     \
    do {                                                                      \
        const h16* ap_ = A + (size_t)(brow + ar) * K + (k0) + ac;             \
        h16* dh_ = &sm[(s) * A_ST_SZ + ar * A_STR + ac];                      \
        cpasync16(dh_, ap_);                                                  \
        cpasync16(dh_ + 8, ap_ + 8);                                          \
        size_t go_ = (size_t)((k0) + br_) * Nc + bcol + bc;                   \
        h16* db_ = &sm[OFF_B + (s) * B_ST_SZ + br_ * B_STR + bc];             \
        cpasync16(db_, B + go_);                                              \
        cpasync16(db_ + 64, B + go_ + 64);                                    \
    } while (0)

#define GEMM_COMPUTE(buf)                                                     \
    do {                                                                      \
        _Pragma("unroll")                                                     \
        for (int kk = 0; kk < 2; kk++) {                                      \
            unsigned ah[2][4];                                                \
            _Pragma("unroll")                                                 \
            for (int mt = 0; mt < 2; mt++) {                                  \
                int off = (buf) * A_ST_SZ + (wm + mt * 16 + lrow) * A_STR +   \
                          kk * 16 + lc8;                                      \
                ldsm4(ah[mt], &sm[off]);                                      \
            }                                                                 \
            _Pragma("unroll")                                                 \
            for (int pr = 0; pr < 4; pr++) {                                  \
                unsigned bh[4];                                               \
                int off = OFF_B + (buf) * B_ST_SZ + (kk * 16 + lrow) * B_STR + \
                          wn + pr * 16 + lc8;                                 \
                ldsm4t(bh, &sm[off]);                                         \
                _Pragma("unroll")                                             \
                for (int mt = 0; mt < 2; mt++) {                              \
                    mma16(acc[mt][2 * pr],     ah[mt], bh[0], bh[1]);         \
                    mma16(acc[mt][2 * pr + 1], ah[mt], bh[2], bh[3]);         \
                }                                                             \
            }                                                                 \
        }                                                                     \
    } while (0)

#define GEMM_MAINLOOP()                                                       \
    do {                                                                      \
        const int T = K / 32;                                                 \
        GEMM_STAGE(0, 0); CP_COMMIT();                                        \
        GEMM_STAGE(1, 32); CP_COMMIT();                                       \
        int buf = 0;                                                          \
        for (int it = 0; it < T; it++) {                                      \
            CP_WAIT1();                                                       \
            __syncthreads();                                                  \
            GEMM_COMPUTE(buf);                                                \
            if (it + 2 < T) {                                                 \
                int s2 = buf + 2; if (s2 >= 3) s2 -= 3;                       \
                GEMM_STAGE(s2, (it + 2) * 32);                                \
            }                                                                 \
            CP_COMMIT();                                                      \
            if (++buf == 3) buf = 0;                                          \
        }                                                                     \
    } while (0)

// ---------------------------------------------------------------------------
// Merged QKV projection: grid (24, 32). blockIdx.x>>3 selects Q|K|V.
// Q scaled by 0.125*log2(e): mma in attention then emits s*log2e directly.
// ---------------------------------------------------------------------------
#define QSCALE 0.18033688011112042f   // log2(e)/8

__global__ __launch_bounds__(256, 2) void qkv_tc(
    const h16* __restrict__ qh_, const h16* __restrict__ ch_,
    const h16* __restrict__ Wq, const h16* __restrict__ Wk,
    const h16* __restrict__ Wv,
    const float* __restrict__ Wqb, const float* __restrict__ Wkb,
    const float* __restrict__ Wvb,
    const float* __restrict__ qnw, const float* __restrict__ qnb,
    const float* __restrict__ knw, const float* __restrict__ knb,
    h16* __restrict__ Qo, h16* __restrict__ Ko, h16* __restrict__ Vo)
{
    extern __shared__ __align__(16) h16 sm[];
    const int tid = threadIdx.x, wid = tid >> 5, lane = tid & 31;
    const int g = lane >> 2, t = lane & 3;
    const int wm = (wid >> 1) * 32, wn = (wid & 1) * 64;
    const int which = blockIdx.x >> 3;
    const int bcol = (blockIdx.x & 7) * 128;
    const int brow = blockIdx.y * 128;
    const int lrow = lane & 15, lc8 = ((lane >> 4) & 1) * 8;
    const int Nc = DD, K = DD;

    const h16* A = (which == 0) ? qh_ : ch_;
    const h16* B = (which == 0) ? Wq : (which == 1) ? Wk : Wv;
    const float* bias = (which == 0) ? Wqb : (which == 1) ? Wkb : Wvb;
    h16* Ch = (which == 0) ? Qo : (which == 1) ? Ko : Vo;

    const int ar = tid >> 1, ac = (tid & 1) * 16;
    const int br_ = tid >> 3, bc = (tid & 7) * 8;

    float acc[2][8][4];
    #pragma unroll
    for (int i = 0; i < 2; i++)
        #pragma unroll
        for (int j = 0; j < 8; j++)
            #pragma unroll
            for (int q = 0; q < 4; q++) acc[i][j][q] = 0.0f;

    GEMM_MAINLOOP();

    if (which < 2) {
        const float* lnw = (which == 0) ? qnw : knw;
        const float* lnb = (which == 0) ? qnb : knb;
        const float lnsc = (which == 0) ? QSCALE : 1.0f;
        #pragma unroll
        for (int mt = 0; mt < 2; mt++) {
            float sA = 0.0f, qA = 0.0f, sB = 0.0f, qB = 0.0f;
            #pragma unroll
            for (int nt = 0; nt < 8; nt++) {
                const int hc = nt * 8 + 2 * t;
                float2 bv = *(const float2*)(bias + bcol + wn + hc);
                float a0 = acc[mt][nt][0] + bv.x;
                float a1 = acc[mt][nt][1] + bv.y;
                float a2 = acc[mt][nt][2] + bv.x;
                float a3 = acc[mt][nt][3] + bv.y;
                acc[mt][nt][0] = a0; acc[mt][nt][1] = a1;
                acc[mt][nt][2] = a2; acc[mt][nt][3] = a3;
                sA += a0 + a1; qA += a0 * a0 + a1 * a1;
                sB += a2 + a3; qB += a2 * a2 + a3 * a3;
            }
            sA += __shfl_xor_sync(0xffffffffu, sA, 1);
            sA += __shfl_xor_sync(0xffffffffu, sA, 2);
            qA += __shfl_xor_sync(0xffffffffu, qA, 1);
            qA += __shfl_xor_sync(0xffffffffu, qA, 2);
            sB += __shfl_xor_sync(0xffffffffu, sB, 1);
            sB += __shfl_xor_sync(0xffffffffu, sB, 2);
            qB += __shfl_xor_sync(0xffffffffu, qB, 1);
            qB += __shfl_xor_sync(0xffffffffu, qB, 2);
            const float muA = sA * (1.0f / 64.0f);
            const float muB = sB * (1.0f / 64.0f);
            const float rA = rsqrtf(qA * (1.0f / 64.0f) - muA * muA + EPS);
            const float rB = rsqrtf(qB * (1.0f / 64.0f) - muB * muB + EPS);
            const int r0 = brow + wm + mt * 16 + g;
            #pragma unroll
            for (int nt = 0; nt < 8; nt++) {
                const int hc = nt * 8 + 2 * t;
                const int c = bcol + wn + hc;
                float2 lw = *(const float2*)(lnw + hc);
                float2 lb = *(const float2*)(lnb + hc);
                float y0 = ((acc[mt][nt][0] - muA) * rA * lw.x + lb.x) * lnsc;
                float y1 = ((acc[mt][nt][1] - muA) * rA * lw.y + lb.y) * lnsc;
                float y2 = ((acc[mt][nt][2] - muB) * rB * lw.x + lb.x) * lnsc;
                float y3 = ((acc[mt][nt][3] - muB) * rB * lw.y + lb.y) * lnsc;
                *(unsigned*)(Ch + (size_t)r0 * Nc + c)       = pack2h(y0, y1);
                *(unsigned*)(Ch + (size_t)(r0 + 8) * Nc + c) = pack2h(y2, y3);
            }
        }
    } else {
        #pragma unroll
        for (int nt = 0; nt < 8; nt++) {
            const int c = bcol + wn + nt * 8 + 2 * t;
            float2 bv = *(const float2*)(bias + c);
            #pragma unroll
            for (int mt = 0; mt < 2; mt++) {
                const int r0 = brow + wm + mt * 16 + g;
                *(unsigned*)(Ch + (size_t)r0 * Nc + c) =
                    pack2h(acc[mt][nt][0] + bv.x, acc[mt][nt][1] + bv.y);
                *(unsigned*)(Ch + (size_t)(r0 + 8) * Nc + c) =
                    pack2h(acc[mt][nt][2] + bv.x, acc[mt][nt][3] + bv.y);
            }
        }
    }
}

// ---------------------------------------------------------------------------
// fp16 GEMM for MLP, templated epilogue.
// ---------------------------------------------------------------------------
template <int EPI>
__global__ __launch_bounds__(256, 2) void gemm_tc(
    const h16* __restrict__ A, const h16* __restrict__ B,
    const float* __restrict__ bias, const float* __restrict__ Res,
    float* __restrict__ Cf, h16* __restrict__ Ch, int Nc, int K)
{
    extern __shared__ __align__(16) h16 sm[];
    const int tid = threadIdx.x, wid = tid >> 5, lane = tid & 31;
    const int g = lane >> 2, t = lane & 3;
    const int wm = (wid >> 1) * 32, wn = (wid & 1) * 64;
    const int brow = blockIdx.y * 128, bcol = blockIdx.x * 128;
    const int lrow = lane & 15, lc8 = ((lane >> 4) & 1) * 8;

    const int ar = tid >> 1, ac = (tid & 1) * 16;
    const int br_ = tid >> 3, bc = (tid & 7) * 8;

    float acc[2][8][4];
    #pragma unroll
    for (int i = 0; i < 2; i++)
        #pragma unroll
        for (int j = 0; j < 8; j++)
            #pragma unroll
            for (int q = 0; q < 4; q++) acc[i][j][q] = 0.0f;

    GEMM_MAINLOOP();

    #pragma unroll
    for (int nt = 0; nt < 8; nt++) {
        const int c = bcol + wn + nt * 8 + 2 * t;
        float2 bv = *(const float2*)(bias + c);
        #pragma unroll
        for (int mt = 0; mt < 2; mt++) {
            const int r0 = brow + wm + mt * 16 + g;
            float2 v0 = make_float2(acc[mt][nt][0] + bv.x, acc[mt][nt][1] + bv.y);
            float2 v1 = make_float2(acc[mt][nt][2] + bv.x, acc[mt][nt][3] + bv.y);
            if (EPI == 2) {
                float2 a0 = *(const float2*)(Res + (size_t)r0 * Nc + c);
                float2 a1 = *(const float2*)(Res + (size_t)(r0 + 8) * Nc + c);
                v0.x += a0.x; v0.y += a0.y; v1.x += a1.x; v1.y += a1.y;
                *(float2*)(Cf + (size_t)r0 * Nc + c) = v0;
                *(float2*)(Cf + (size_t)(r0 + 8) * Nc + c) = v1;
            } else {
                v0.x = gelu_exact(v0.x); v0.y = gelu_exact(v0.y);
                v1.x = gelu_exact(v1.x); v1.y = gelu_exact(v1.y);
                *(unsigned*)(Ch + (size_t)r0 * Nc + c) = pack2h(v0.x, v0.y);
                *(unsigned*)(Ch + (size_t)(r0 + 8) * Nc + c) = pack2h(v1.x, v1.y);
            }
        }
    }
}

// ---------------------------------------------------------------------------
// fp16 flash attention, bounded-max softmax with exp folded into Q scale.
// Q TILE = 256 rows, 512 threads / 16 warps, ONE block per SM: each SM stages
// every KV tile ONCE (vs twice with 2x256-thr blocks) — halves cp.async +
// smem-store traffic per q-row. Each warp still owns 16 q rows.
// smem h16: K[3][64][72] | V[3][64][72] -> 55296 bytes
// ---------------------------------------------------------------------------
#define KV_STR 72
#define KV_ST_SZ (64 * KV_STR)
#define OFF_V (3 * KV_ST_SZ)
#define ATTN_SMEM_BYTES ((OFF_V + 3 * KV_ST_SZ) * 2)
#define ONES2 0x3C003C00u

__global__ __launch_bounds__(512, 1) void attn_tc(
    const h16* __restrict__ Qh_, const h16* __restrict__ Kh_,
    const h16* __restrict__ Vh_,
    const float* __restrict__ Res, float* __restrict__ Out)
{
    extern __shared__ __align__(16) h16 sm[];
    const int b = blockIdx.z, h = blockIdx.y, q0 = blockIdx.x * 256;
    const int tid = threadIdx.x, w = tid >> 5, lane = tid & 31;
    const int g = lane >> 2, t = lane & 3;
    const int lrow = lane & 15, lc8 = ((lane >> 4) & 1) * 8;
    const size_t hoff = (size_t)h * HD;

    // staging: 512 threads, 64x64 K + V tile; thread -> row tid>>3,
    // 16B chunk at col (tid&7)*8; 1 K chunk + 1 V chunk per thread.
    const int sr = tid >> 3, sc8 = (tid & 7) * 8;
    auto stageKV = [&](int s, int c0) {
        size_t go = ((size_t)(b * MM + c0 + sr)) * DD + hoff + sc8;
        int off = s * KV_ST_SZ + sr * KV_STR + sc8;
        cpasync16(&sm[off],         Kh_ + go);
        cpasync16(&sm[OFF_V + off], Vh_ + go);
    };

    stageKV(0, 0); CP_COMMIT();
    stageKV(1, 64); CP_COMMIT();

    unsigned qh[4][4];
    {
        size_t r0 = ((size_t)(b * NN + q0 + w * 16 + g)) * DD + hoff;
        size_t r1 = r0 + 8 * DD;
        #pragma unroll
        for (int kk = 0; kk < 4; kk++) {
            int c0 = kk * 16 + 2 * t;
            qh[kk][0] = *(const unsigned*)(Qh_ + r0 + c0);
            qh[kk][1] = *(const unsigned*)(Qh_ + r1 + c0);
            qh[kk][2] = *(const unsigned*)(Qh_ + r0 + c0 + 8);
            qh[kk][3] = *(const unsigned*)(Qh_ + r1 + c0 + 8);
        }
    }

    float o[8][4];
    #pragma unroll
    for (int i = 0; i < 8; i++)
        #pragma unroll
        for (int j = 0; j < 4; j++) o[i][j] = 0.0f;
    float accl[4] = {0.0f, 0.0f, 0.0f, 0.0f};

    const int T = MM / 64;
    int buf = 0;
    for (int it = 0; it < T; it++) {
        CP_WAIT1();
        __syncthreads();

        float s[8][4];
        #pragma unroll
        for (int i = 0; i < 8; i++)
            #pragma unroll
            for (int j = 0; j < 4; j++) s[i][j] = 0.0f;

        #pragma unroll
        for (int kk = 0; kk < 4; kk++) {
            #pragma unroll
            for (int kp = 0; kp < 4; kp++) {
                unsigned kh[4];
                int off = buf * KV_ST_SZ + (kp * 16 + lrow) * KV_STR + kk * 16 + lc8;
                ldsm4(kh, &sm[off]);
                mma16(s[2 * kp],     qh[kk], kh[0], kh[2]);
                mma16(s[2 * kp + 1], qh[kk], kh[1], kh[3]);
            }
        }

        // P~ = exp2(s) directly (s already includes the log2e/8 scale)
        #pragma unroll
        for (int kk = 0; kk < 4; kk++) {
            unsigned ph[4];
            ph[0] = h2exp2u(pack2h(s[2 * kk][0],     s[2 * kk][1]));
            ph[1] = h2exp2u(pack2h(s[2 * kk][2],     s[2 * kk][3]));
            ph[2] = h2exp2u(pack2h(s[2 * kk + 1][0], s[2 * kk + 1][1]));
            ph[3] = h2exp2u(pack2h(s[2 * kk + 1][2], s[2 * kk + 1][3]));
            mma16(accl, ph, ONES2, ONES2);
            #pragma unroll
            for (int dp = 0; dp < 4; dp++) {
                unsigned vh[4];
                int off = buf * KV_ST_SZ + (kk * 16 + lrow) * KV_STR + dp * 16 + lc8;
                ldsm4t(vh, &sm[OFF_V + off]);
                mma16(o[2 * dp],     ph, vh[0], vh[1]);
                mma16(o[2 * dp + 1], ph, vh[2], vh[3]);
            }
        }

        if (it + 2 < T) {
            int s2 = buf + 2; if (s2 >= 3) s2 -= 3;
            stageKV(s2, (it + 2) * 64);
        }
        CP_COMMIT();
        if (++buf == 3) buf = 0;
    }

    const float i0 = 1.0f / accl[0], i1 = 1.0f / accl[2];
    size_t base0 = ((size_t)(b * NN + q0 + w * 16 + g)) * DD + hoff;
    size_t base1 = base0 + 8 * DD;
    #pragma unroll
    for (int nt = 0; nt < 8; nt++) {
        int c = nt * 8 + 2 * t;
        float2 r0v = *(const float2*)(Res + base0 + c);
        float2 r1v = *(const float2*)(Res + base1 + c);
        float2 v0 = make_float2(o[nt][0] * i0 + r0v.x, o[nt][1] * i0 + r0v.y);
        float2 v1 = make_float2(o[nt][2] * i1 + r1v.x, o[nt][3] * i1 + r1v.y);
        *(float2*)(Out + base0 + c) = v0;
        *(float2*)(Out + base1 + c) = v1;
    }
}

// ---------------------------------------------------------------------------
// Row LayerNorm over D=1024 -> fp16.
// ---------------------------------------------------------------------------
__global__ __launch_bounds__(256) void row_ln_pl(
    const float* __restrict__ x, const float* __restrict__ w,
    const float* __restrict__ b, h16* __restrict__ yh)
{
    const int row = blockIdx.x;
    const int tid = threadIdx.x;
    float4 v = ((const float4*)(x + (size_t)row * DD))[tid];
    float s  = v.x + v.y + v.z + v.w;
    float ss = v.x * v.x + v.y * v.y + v.z * v.z + v.w * v.w;
    #pragma unroll
    for (int o = 16; o; o >>= 1) {
        s  += __shfl_xor_sync(0xffffffffu, s, o);
        ss += __shfl_xor_sync(0xffffffffu, ss, o);
    }
    __shared__ float smm[8], sm2[8];
    if ((tid & 31) == 0) { smm[tid >> 5] = s; sm2[tid >> 5] = ss; }
    __syncthreads();
    if (tid < 32) {
        float a  = (tid < 8) ? smm[tid] : 0.0f;
        float a2 = (tid < 8) ? sm2[tid] : 0.0f;
        #pragma unroll
        for (int o = 4; o; o >>= 1) {
            a  += __shfl_xor_sync(0xffffffffu, a, o);
            a2 += __shfl_xor_sync(0xffffffffu, a2, o);
        }
        if (tid == 0) { smm[0] = a; sm2[0] = a2; }
    }
    __syncthreads();
    float mu  = smm[0] * (1.0f / (float)DD);
    float var = sm2[0] * (1.0f / (float)DD) - mu * mu;
    float r = rsqrtf(var + EPS);
    float4 ww = ((const float4*)w)[tid];
    float4 bb = ((const float4*)b)[tid];
    float y0 = (v.x - mu) * r * ww.x + bb.x;
    float y1 = (v.y - mu) * r * ww.y + bb.y;
    float y2 = (v.z - mu) * r * ww.z + bb.z;
    float y3 = (v.w - mu) * r * ww.w + bb.w;
    size_t off = (size_t)row * DD + tid * 4;
    *(unsigned*)(yh + off)     = pack2h(y0, y1);
    *(unsigned*)(yh + off + 2) = pack2h(y2, y3);
}

// ---------------------------------------------------------------------------
extern "C" void kernel_launch(void* const* d_in, const int* in_sizes, int n_in,
                              void* d_out, int out_size)
{
    const float* query   = (const float*)d_in[0];
    const float* context = (const float*)d_in[1];
    const float* Wq_w = (const float*)d_in[4];
    const float* Wq_b = (const float*)d_in[5];
    const float* Wk_w = (const float*)d_in[6];
    const float* Wk_b = (const float*)d_in[7];
    const float* Wv_w = (const float*)d_in[8];
    const float* Wv_b = (const float*)d_in[9];
    const float* qn_w = (const float*)d_in[10];
    const float* qn_b = (const float*)d_in[11];
    const float* kn_w = (const float*)d_in[12];
    const float* kn_b = (const float*)d_in[13];
    const float* ffn_w = (const float*)d_in[14];
    const float* ffn_b = (const float*)d_in[15];
    const float* fc1_w = (const float*)d_in[16];
    const float* fc1_b = (const float*)d_in[17];
    const float* fc2_w = (const float*)d_in[18];
    const float* fc2_b = (const float*)d_in[19];
    float* out = (float*)d_out;

    float* X;
    h16 *qh, *ch, *Wq, *Wk, *Wv, *F1, *F2, *Qh, *Kh, *Vh, *Lh, *Hh;
    cudaGetSymbolAddress((void**)&X, gX);
    cudaGetSymbolAddress((void**)&qh, gqh); cudaGetSymbolAddress((void**)&ch, gch);
    cudaGetSymbolAddress((void**)&Wq, gWq); cudaGetSymbolAddress((void**)&Wk, gWk);
    cudaGetSymbolAddress((void**)&Wv, gWv);
    cudaGetSymbolAddress((void**)&F1, gF1); cudaGetSymbolAddress((void**)&F2, gF2);
    cudaGetSymbolAddress((void**)&Qh, gQh); cudaGetSymbolAddress((void**)&Kh, gKh);
    cudaGetSymbolAddress((void**)&Vh, gVh);
    cudaGetSymbolAddress((void**)&Lh, gLh); cudaGetSymbolAddress((void**)&Hh, gHh);

    static bool attr_done = false;
    if (!attr_done) {
        cudaFuncSetAttribute(qkv_tc, cudaFuncAttributeMaxDynamicSharedMemorySize,
                             GEMM_SMEM_BYTES);
        cudaFuncSetAttribute(gemm_tc<1>, cudaFuncAttributeMaxDynamicSharedMemorySize,
                             GEMM_SMEM_BYTES);
        cudaFuncSetAttribute(gemm_tc<2>, cudaFuncAttributeMaxDynamicSharedMemorySize,
                             GEMM_SMEM_BYTES);
        cudaFuncSetAttribute(attn_tc, cudaFuncAttributeMaxDynamicSharedMemorySize,
                             ATTN_SMEM_BYTES);
        attr_done = true;
    }

    const int Rows = BB * NN;  // 4096
    const size_t actN = (size_t)BB * NN * DD;

    ConvJobs jb;
    jb.src[0] = (const float4*)query;   jb.dst[0] = (unsigned*)qh; jb.n4[0] = (int)(actN / 4);
    jb.src[1] = (const float4*)context; jb.dst[1] = (unsigned*)ch; jb.n4[1] = (int)(actN / 4);
    jb.src[2] = (const float4*)Wq_w;    jb.dst[2] = (unsigned*)Wq; jb.n4[2] = DD * DD / 4;
    jb.src[3] = (const float4*)Wk_w;    jb.dst[3] = (unsigned*)Wk; jb.n4[3] = DD * DD / 4;
    jb.src[4] = (const float4*)Wv_w;    jb.dst[4] = (unsigned*)Wv; jb.n4[4] = DD * DD / 4;
    jb.src[5] = (const float4*)fc1_w;   jb.dst[5] = (unsigned*)F1; jb.n4[5] = (int)((size_t)DD * FF / 4);
    jb.src[6] = (const float4*)fc2_w;   jb.dst[6] = (unsigned*)F2; jb.n4[6] = (int)((size_t)FF * DD / 4);
    conv_batch<<<dim3(1024, NCONV), 256>>>(jb);

    // merged QKV projections (Q/K with fused per-head LN; Q scaled by log2e/8)
    qkv_tc<<<dim3(24, Rows / 128), 256, GEMM_SMEM_BYTES>>>(
        qh, ch, Wq, Wk, Wv, Wq_b, Wk_b, Wv_b,
        qn_w, qn_b, kn_w, kn_b, Qh, Kh, Vh);

    // flash attention + residual -> X (fp32); q-tile 256, 512 threads
    attn_tc<<<dim3(NN / 256, HH, BB), 512, ATTN_SMEM_BYTES>>>(Qh, Kh, Vh, query, X);

    // pre-MLP LN -> fp16
    row_ln_pl<<<Rows, 256>>>(X, ffn_w, ffn_b, Lh);

    // fc1 + GELU -> fp16
    gemm_tc<1><<<dim3(FF / 128, Rows / 128), 256, GEMM_SMEM_BYTES>>>(
        Lh, F1, fc1_b, nullptr, nullptr, Hh, FF, DD);
    // fc2 + residual(X) -> out (fp32)
    gemm_tc<2><<<dim3(DD / 128, Rows / 128), 256, GEMM_SMEM_BYTES>>>(
        Hh, F2, fc2_b, X, out, nullptr, DD, FF);
}